// round 13
// baseline (speedup 1.0000x reference)
#include <cuda_runtime.h>
#include <math.h>

#define HH 1024
#define WW 1024
#define PLANES 24           // 8 batch * 3 channels
#define RAD 25
#define TAPS 51
#define PSTEP 3             // planes per pipeline step (24/3 = 8 H-steps)

// 100 MB scratch for the horizontal-pass result (no cudaMalloc allowed)
__device__ float g_tmp[(size_t)PLANES * HH * WW];

// ---------------- compile-time gaussian weights -> FFMA immediates ----------
struct WTab { float w[TAPS]; };

__host__ __device__ constexpr double cexp_series(double x) {
    double term = 1.0, sum = 1.0;
    for (int i = 1; i < 40; ++i) { term *= x / (double)i; sum += term; }
    return sum;
}

__host__ __device__ constexpr WTab make_wtab() {
    WTab t{};
    double g[TAPS] = {};
    double s = 0.0;
    for (int i = 0; i < TAPS; ++i) {
        double d = (double)(i - RAD);
        g[i] = cexp_series(-d * d / (2.0 * 15.0 * 15.0));
        s += g[i];
    }
    for (int i = 0; i < TAPS; ++i) t.w[i] = (float)(g[i] / s);
    return t;
}

__constant__ WTab c_wt = make_wtab();

// ---------------- packed f32x2 helpers (V body) ---------------------------
__device__ __forceinline__ unsigned long long pk2(float a, float b) {
    unsigned long long r;
    asm("mov.b64 %0, {%1, %2};" : "=l"(r) : "f"(a), "f"(b));
    return r;
}
__device__ __forceinline__ void upk2(unsigned long long v, float& a, float& b) {
    asm("mov.b64 {%0, %1}, %2;" : "=f"(a), "=f"(b) : "l"(v));
}
__device__ __forceinline__ unsigned long long ffma2(unsigned long long a,
                                                    unsigned long long b,
                                                    unsigned long long c) {
    unsigned long long d;
    asm("fma.rn.f32x2 %0, %1, %2, %3;" : "=l"(d) : "l"(a), "l"(b), "l"(c));
    return d;
}

#define TYV 32
#define SRV (TYV + 2 * RAD)     // 82
// dyn smem layout: [wb: 51 ull = 104 floats | vtile: 82*128 floats]  (H uses prefix)
#define SMEM_FLOATS (104 + SRV * 128)

extern __shared__ float smn[];

// ---------------- H body: one image row, 256 threads, 4 outputs/thread ------
// (R9 hpass verbatim; LDS.128 window, consecutive lanes -> conflict-free,
//  compile-time weights -> FFMA-imm @ rt1)
__device__ __forceinline__ void h_body(const float* __restrict__ x, int row) {
    const float* src = x + (size_t)row * WW;
    float* dst = g_tmp + (size_t)row * WW;
    float* s = smn;                                    // 1080 floats

    const int tid = threadIdx.x;
    #pragma unroll
    for (int t = 0; t < 5; ++t) {
        int i = tid + t * 256;
        if (i < WW + 2 * RAD + 6) {
            int j = i - RAD;
            s[i] = (j >= 0 && j < WW) ? src[j] : 0.0f;
        }
    }
    __syncthreads();

    constexpr WTab WT = make_wtab();
    const int b = tid * 4;
    const float4* s4 = reinterpret_cast<const float4*>(s);

    float acc[4] = {0.f, 0.f, 0.f, 0.f};
    #pragma unroll
    for (int k4 = 0; k4 < 14; ++k4) {
        float4 v4 = s4[tid + k4];
        float vv[4] = {v4.x, v4.y, v4.z, v4.w};
        #pragma unroll
        for (int q = 0; q < 4; ++q) {
            const int k = 4 * k4 + q;
            #pragma unroll
            for (int i = 0; i < 4; ++i) {
                if (k - i >= 0 && k - i <= 2 * RAD)
                    acc[i] += WT.w[k - i] * vv[q];     // FFMA-imm
            }
        }
    }

    *reinterpret_cast<float4*>(dst + b) = make_float4(acc[0], acc[1], acc[2], acc[3]);
}

// ---------------- V body: 128x32 tile, 256 threads, 8 rows x 2 cols, FFMA2 --
// (R9 vpass verbatim on dynamic smem)
__device__ __forceinline__ void v_body(const float* __restrict__ x, float kk,
                                       float* __restrict__ out,
                                       int plane, int x0, int y0) {
    unsigned long long* wb = reinterpret_cast<unsigned long long*>(smn);
    float (*s)[128] = reinterpret_cast<float (*)[128]>(smn + 104);

    const int tid = threadIdx.x;
    if (tid < TAPS) wb[tid] = pk2(c_wt.w[tid], c_wt.w[tid]);

    const float* tp = g_tmp + (size_t)plane * HH * WW;

    #pragma unroll
    for (int t = 0; t < 11; ++t) {                   // 11*256 >= 82*32
        int i = tid + t * 256;
        if (i < SRV * 32) {
            int r = i >> 5, c4 = (i & 31) << 2;
            int gy = y0 - RAD + r;
            float4 v = make_float4(0.f, 0.f, 0.f, 0.f);
            if ((unsigned)gy < HH)
                v = *reinterpret_cast<const float4*>(tp + (size_t)gy * WW + x0 + c4);
            *reinterpret_cast<float4*>(&s[r][c4]) = v;
        }
    }
    __syncthreads();

    const int p = tid & 63;          // column pair (cols 2p, 2p+1)
    const int h = tid >> 6;          // row quarter: 8 rows
    const int rbase = h * 8;

    unsigned long long v[8];
    #pragma unroll
    for (int j = 0; j < 7; ++j)
        v[j] = *reinterpret_cast<const unsigned long long*>(&s[rbase + j][2 * p]);

    unsigned long long acc[8];
    #pragma unroll
    for (int i = 0; i < 8; ++i) acc[i] = 0ull;

    #pragma unroll
    for (int d = 0; d <= 50; ++d) {
        v[(d + 7) & 7] =
            *reinterpret_cast<const unsigned long long*>(&s[rbase + d + 7][2 * p]);
        unsigned long long wd = wb[d];
        #pragma unroll
        for (int ii = 0; ii < 8; ++ii)
            acc[ii] = ffma2(v[(d + ii) & 7], wd, acc[ii]);
    }

    const float* xp = x + (size_t)plane * HH * WW;
    float* op = out + (size_t)plane * HH * WW;

    #pragma unroll
    for (int ii = 0; ii < 8; ++ii) {
        const int gy = y0 + rbase + ii;
        const size_t off = (size_t)gy * WW + x0 + 2 * p;
        float2 xv = *reinterpret_cast<const float2*>(xp + off);
        float b0, b1;
        upk2(acc[ii], b0, b1);
        float r0 = xv.x + b0 * kk * (1.0f - xv.x);
        float r1 = xv.y + b1 * kk * (1.0f - xv.y);
        r0 = fminf(fmaxf(r0, 0.0f), 1.0f);
        r1 = fminf(fmaxf(r1, 0.0f), 1.0f);
        *reinterpret_cast<float2*>(op + off) = make_float2(r0, r1);
    }
}

// ---------------- pipelined step: H(planes hb..hb+NH-1) || V(vb..vb+NV-1) ---
// V reads g_tmp written by the PREVIOUS launch -> no intra-kernel dependency.
// Blocks interleaved 4H:1V by index so both mixes co-reside on each SM.
__global__ void __launch_bounds__(256) step_kernel(const float* __restrict__ x,
                                                   const float* __restrict__ amt_p,
                                                   float* __restrict__ out,
                                                   int hb, int vb, int NH, int NV) {
    const float kk = 1.2f * (0.4f / (1.0f + expf(-amt_p[0])));

    const int bid = blockIdx.x;
    bool isV;
    int idx;
    if (NV == 0)      { isV = false; idx = bid; }
    else if (NH == 0) { isV = true;  idx = bid; }
    else {                                   // NH==NV==PSTEP: 4 H per 1 V
        const int q = bid / 5, r = bid - q * 5;
        isV = (r == 4);
        idx = isV ? q : q * 4 + r;
    }

    if (isV) {
        const int plane = vb + (idx >> 8);           // 256 V blocks per plane
        const int v = idx & 255;
        v_body(x, kk, out, plane, (v & 7) * 128, (v >> 3) * TYV);
    } else {
        h_body(x, hb * HH + idx);                    // 1024 H blocks per plane
    }
}

extern "C" void kernel_launch(void* const* d_in, const int* in_sizes, int n_in,
                              void* d_out, int out_size) {
    const float* x   = (const float*)d_in[0];
    const float* amt = (const float*)d_in[1];
    float* out = (float*)d_out;

    const int smem = SMEM_FLOATS * (int)sizeof(float);   // 42400 B (< 48K default)
    const int nsteps = PLANES / PSTEP + 1;               // 9

    for (int s = 0; s < nsteps; ++s) {
        const int NH = (s < PLANES / PSTEP) ? PSTEP : 0;
        const int NV = (s > 0) ? PSTEP : 0;
        const int hb = PSTEP * s;
        const int vb = PSTEP * (s - 1);
        const int grid = NH * HH + NV * 256;
        step_kernel<<<grid, 256, smem>>>(x, amt, out, hb, vb, NH, NV);
    }
}

// round 15
// speedup vs baseline: 1.7241x; 1.7241x over previous
#include <cuda_runtime.h>
#include <math.h>

#define HH 1024
#define WW 1024
#define PLANES 24           // 8 batch * 3 channels
#define RAD 25
#define TAPS 51

// 100 MB scratch for the horizontal-pass result (no cudaMalloc allowed)
__device__ float g_tmp[(size_t)PLANES * HH * WW];

// ---------------- compile-time gaussian weights -> FFMA immediates ----------
struct WTab { float w[TAPS]; };

__host__ __device__ constexpr double cexp_series(double x) {
    double term = 1.0, sum = 1.0;
    for (int i = 1; i < 40; ++i) { term *= x / (double)i; sum += term; }
    return sum;
}

__host__ __device__ constexpr WTab make_wtab() {
    WTab t{};
    double g[TAPS] = {};
    double s = 0.0;
    for (int i = 0; i < TAPS; ++i) {
        double d = (double)(i - RAD);
        g[i] = cexp_series(-d * d / (2.0 * 15.0 * 15.0));
        s += g[i];
    }
    for (int i = 0; i < TAPS; ++i) t.w[i] = (float)(g[i] / s);
    return t;
}

// ---------------- pass 1: horizontal 51-tap conv (R9 verbatim) --------------
// One block = one image row, 256 threads, 4 outputs/thread.
// LDS.128 window: consecutive lanes -> consecutive 16B -> conflict-free.
__global__ void __launch_bounds__(256) hpass(const float* __restrict__ x) {
    const int row = blockIdx.x;                       // 0 .. PLANES*HH-1
    const float* src = x + (size_t)row * WW;
    float* dst = g_tmp + (size_t)row * WW;

    __shared__ __align__(16) float s[WW + 2 * RAD + 6];   // 1080 floats

    const int tid = threadIdx.x;
    #pragma unroll
    for (int t = 0; t < 5; ++t) {                    // 5*256 >= 1080
        int i = tid + t * 256;
        if (i < WW + 2 * RAD + 6) {
            int j = i - RAD;
            s[i] = (j >= 0 && j < WW) ? src[j] : 0.0f;
        }
    }
    __syncthreads();

    constexpr WTab WT = make_wtab();
    const int b = tid * 4;                           // outputs b..b+3
    const float4* s4 = reinterpret_cast<const float4*>(s);

    float acc[4] = {0.f, 0.f, 0.f, 0.f};
    #pragma unroll
    for (int k4 = 0; k4 < 14; ++k4) {                // window floats 0..55
        float4 v4 = s4[tid + k4];
        float vv[4] = {v4.x, v4.y, v4.z, v4.w};
        #pragma unroll
        for (int q = 0; q < 4; ++q) {
            const int k = 4 * k4 + q;
            #pragma unroll
            for (int i = 0; i < 4; ++i) {
                if (k - i >= 0 && k - i <= 2 * RAD)
                    acc[i] += WT.w[k - i] * vv[q];   // compile-time w -> FFMA-imm
            }
        }
    }

    *reinterpret_cast<float4*>(dst + b) = make_float4(acc[0], acc[1], acc[2], acc[3]);
}

// ---------------- pass 2: streaming vertical conv + blend (no smem) --------
// Thread-per-column: warp = 32 consecutive cols -> every row read is one
// coalesced 128B line. 16 output rows per thread, 66 scalar LDGs slide down
// the column, FFMA-imm weights, zero barriers, zero shared memory.
#define VROWS 16

__global__ void __launch_bounds__(256) vpass(const float* __restrict__ x,
                                             const float* __restrict__ amt_p,
                                             float* __restrict__ out) {
    const int tid = threadIdx.x;
    const int plane = blockIdx.z;
    const int c  = blockIdx.x * 256 + tid;           // column 0..1023
    const int y0 = blockIdx.y * VROWS;               // first output row

    const float* tp = g_tmp + (size_t)plane * HH * WW + c;

    constexpr WTab WT = make_wtab();

    float acc[VROWS];
    #pragma unroll
    for (int i = 0; i < VROWS; ++i) acc[i] = 0.0f;

    // rows y0-25 .. y0+40 (66 loads); out-of-range rows contribute 0
    #pragma unroll
    for (int k = 0; k < VROWS + 2 * RAD; ++k) {
        const int gy = y0 - RAD + k;
        const float v = ((unsigned)gy < HH) ? __ldg(tp + (size_t)gy * WW) : 0.0f;
        #pragma unroll
        for (int i = 0; i < VROWS; ++i) {
            if (k - i >= 0 && k - i <= 2 * RAD)
                acc[i] += WT.w[k - i] * v;           // FFMA-imm
        }
    }

    // amount = sigmoid(param)*0.4 ; result = clip(x + blur*1.2*amount*(1-x))
    const float kk = 1.2f * (0.4f / (1.0f + expf(-amt_p[0])));

    const float* xp = x + (size_t)plane * HH * WW + c;
    float* op = out + (size_t)plane * HH * WW + c;

    #pragma unroll
    for (int i = 0; i < VROWS; ++i) {
        const size_t off = (size_t)(y0 + i) * WW;
        const float xv = __ldg(xp + off);
        float r = fmaf(acc[i] * kk, 1.0f - xv, xv);
        op[off] = fminf(fmaxf(r, 0.0f), 1.0f);
    }
}

extern "C" void kernel_launch(void* const* d_in, const int* in_sizes, int n_in,
                              void* d_out, int out_size) {
    const float* x   = (const float*)d_in[0];
    const float* amt = (const float*)d_in[1];
    float* out = (float*)d_out;

    hpass<<<PLANES * HH, 256>>>(x);
    dim3 grid(WW / 256, HH / VROWS, PLANES);         // (4, 64, 24) = 6144 blocks
    vpass<<<grid, 256>>>(x, amt, out);
}

// round 16
// speedup vs baseline: 1.8224x; 1.0570x over previous
#include <cuda_runtime.h>
#include <math.h>

#define HH 1024
#define WW 1024
#define PLANES 24           // 8 batch * 3 channels
#define RAD 25
#define TAPS 51

// 100 MB scratch for the horizontal-pass result (no cudaMalloc allowed)
__device__ float g_tmp[(size_t)PLANES * HH * WW];

// ---------------- compile-time gaussian weights -> FFMA immediates ----------
struct WTab { float w[TAPS]; };

__host__ __device__ constexpr double cexp_series(double x) {
    double term = 1.0, sum = 1.0;
    for (int i = 1; i < 40; ++i) { term *= x / (double)i; sum += term; }
    return sum;
}

__host__ __device__ constexpr WTab make_wtab() {
    WTab t{};
    double g[TAPS] = {};
    double s = 0.0;
    for (int i = 0; i < TAPS; ++i) {
        double d = (double)(i - RAD);
        g[i] = cexp_series(-d * d / (2.0 * 15.0 * 15.0));
        s += g[i];
    }
    for (int i = 0; i < TAPS; ++i) t.w[i] = (float)(g[i] / s);
    return t;
}

// ---------------- pass 1: horizontal 51-tap conv, pipelined 8 rows/block ----
// Double-buffered smem + register prefetch: LDG for row r+1 issues before
// computing row r -> staging DRAM latency hidden. One barrier per row.
// Compute body identical to R9/R15 (LDS.128 window, FFMA-imm weights).
#define HR 8
#define SROW 1088           // smem floats per row buffer (1080 used, f4-padded)

__global__ void __launch_bounds__(256) hpass(const float* __restrict__ x) {
    const int row0 = blockIdx.x * HR;
    __shared__ __align__(16) float s[2][SROW];

    const int tid = threadIdx.x;
    constexpr WTab WT = make_wtab();

    float px[5];
    {   // prefetch row 0
        const float* src = x + (size_t)row0 * WW;
        #pragma unroll
        for (int t = 0; t < 5; ++t) {
            const int i = tid + t * 256;
            const int j = i - RAD;
            px[t] = (j >= 0 && j < WW) ? __ldg(src + j) : 0.0f;
        }
    }

    #pragma unroll 1
    for (int r = 0; r < HR; ++r) {
        float* sb = s[r & 1];
        #pragma unroll
        for (int t = 0; t < 5; ++t) {
            const int i = tid + t * 256;
            if (i < SROW) sb[i] = px[t];
        }
        if (r + 1 < HR) {     // prefetch next row; latency hidden by compute
            const float* src = x + (size_t)(row0 + r + 1) * WW;
            #pragma unroll
            for (int t = 0; t < 5; ++t) {
                const int i = tid + t * 256;
                const int j = i - RAD;
                px[t] = (j >= 0 && j < WW) ? __ldg(src + j) : 0.0f;
            }
        }
        __syncthreads();      // sb complete; prior compute done (buffer safety)

        const float4* s4 = reinterpret_cast<const float4*>(sb);
        float acc[4] = {0.f, 0.f, 0.f, 0.f};
        #pragma unroll
        for (int k4 = 0; k4 < 14; ++k4) {            // window floats 0..55
            const float4 v4 = s4[tid + k4];          // consecutive lanes, no conflict
            const float vv[4] = {v4.x, v4.y, v4.z, v4.w};
            #pragma unroll
            for (int q = 0; q < 4; ++q) {
                const int k = 4 * k4 + q;
                #pragma unroll
                for (int i = 0; i < 4; ++i) {
                    if (k - i >= 0 && k - i <= 2 * RAD)
                        acc[i] += WT.w[k - i] * vv[q];   // FFMA-imm (rt1)
                }
            }
        }

        float* dst = g_tmp + (size_t)(row0 + r) * WW + tid * 4;
        *reinterpret_cast<float4*>(dst) = make_float4(acc[0], acc[1], acc[2], acc[3]);
    }
}

// ---------------- pass 2: streaming vertical conv + blend (no smem) --------
// Thread-per-column, 32 output rows/thread: 82 coalesced scalar LDGs slide
// down the column into 32 FFMA-imm accumulators. No barriers, no shared mem.
#define VROWS 32

__global__ void __launch_bounds__(256) vpass(const float* __restrict__ x,
                                             const float* __restrict__ amt_p,
                                             float* __restrict__ out) {
    const int tid = threadIdx.x;
    const int plane = blockIdx.z;
    const int c  = blockIdx.x * 256 + tid;           // column 0..1023
    const int y0 = blockIdx.y * VROWS;               // first output row

    const float* tp = g_tmp + (size_t)plane * HH * WW + c;

    constexpr WTab WT = make_wtab();

    float acc[VROWS];
    #pragma unroll
    for (int i = 0; i < VROWS; ++i) acc[i] = 0.0f;

    // rows y0-25 .. y0+56 (82 loads); out-of-range rows contribute 0
    #pragma unroll
    for (int k = 0; k < VROWS + 2 * RAD; ++k) {
        const int gy = y0 - RAD + k;
        const float v = ((unsigned)gy < HH) ? __ldg(tp + (size_t)gy * WW) : 0.0f;
        #pragma unroll
        for (int i = 0; i < VROWS; ++i) {
            if (k - i >= 0 && k - i <= 2 * RAD)
                acc[i] += WT.w[k - i] * v;           // FFMA-imm (rt1)
        }
    }

    // amount = sigmoid(param)*0.4 ; result = clip(x + blur*1.2*amount*(1-x))
    const float kk = 1.2f * (0.4f / (1.0f + expf(-amt_p[0])));

    const float* xp = x + (size_t)plane * HH * WW + c;
    float* op = out + (size_t)plane * HH * WW + c;

    #pragma unroll
    for (int i = 0; i < VROWS; ++i) {
        const size_t off = (size_t)(y0 + i) * WW;
        const float xv = __ldg(xp + off);
        float r = fmaf(acc[i] * kk, 1.0f - xv, xv);
        op[off] = fminf(fmaxf(r, 0.0f), 1.0f);
    }
}

extern "C" void kernel_launch(void* const* d_in, const int* in_sizes, int n_in,
                              void* d_out, int out_size) {
    const float* x   = (const float*)d_in[0];
    const float* amt = (const float*)d_in[1];
    float* out = (float*)d_out;

    hpass<<<PLANES * HH / HR, 256>>>(x);
    dim3 grid(WW / 256, HH / VROWS, PLANES);         // (4, 32, 24) = 3072 blocks
    vpass<<<grid, 256>>>(x, amt, out);
}